// round 14
// baseline (speedup 1.0000x reference)
#include <cuda_runtime.h>
#include <cuda_bf16.h>
#include <cstdint>

#define B_   8
#define T_   512
#define H_   768
#define L_   12
#define FF_  3072
#define BT_  (B_*T_)
#define EPS_ 1e-5f

#define H2_  (H_*H_)
#define HFF_ (H_*FF_)
#define WL_  (5*H2_ + 2*HFF_)
#define WTOT_ ((size_t)L_*WL_ + H2_)

#define OWK_ 0
#define OWV_ (1*H2_)
#define OWR_ (2*H2_)
#define OWO_ (3*H2_)
#define OFR_ (4*H2_)
#define OFK_ (5*H2_)
#define OFV_ (5*H2_ + HFF_)

// ---------------- scratch (static device globals; no allocation) ----------
__device__ float g_h[BT_*H_];
__device__ float g_k[BT_*H_];
__device__ float g_v[BT_*H_];
__device__ float g_r[BT_*H_];

// packed, pre-swizzled operand buffers (hi/lo halves per block)
// A blocks: 128 rows x 32 cols, hi 8KB + lo 8KB = 16KB per block
// W blocks:  96 rows x 32 cols, hi 6KB + lo 6KB = 12KB per block
__device__ __align__(1024) char g_wp [WTOT_*4];
__device__ __align__(1024) char g_xkp[(size_t)BT_*H_*4];
__device__ __align__(1024) char g_xvp[(size_t)BT_*H_*4];
__device__ __align__(1024) char g_xrp[(size_t)BT_*H_*4];
__device__ __align__(1024) char g_atp[(size_t)BT_*H_*4];
__device__ __align__(1024) char g_kfp[(size_t)BT_*FF_*4];

// ---------------- helpers ---------------------------------------------------
__device__ __forceinline__ void fsplit(float x, __nv_bfloat16& h, __nv_bfloat16& l) {
    h = __float2bfloat16_rn(x);
    l = __float2bfloat16_rn(x - __bfloat162float(h));
}

__device__ __forceinline__ float bsum256(float val, float* red) {
    int lane = threadIdx.x & 31;
    int w    = threadIdx.x >> 5;
#pragma unroll
    for (int o = 16; o; o >>= 1) val += __shfl_xor_sync(0xffffffffu, val, o);
    __syncthreads();
    if (lane == 0) red[w] = val;
    __syncthreads();
    float s = 0.f;
#pragma unroll
    for (int i = 0; i < 8; i++) s += red[i];
    return s;
}

// swizzled 16B-chunk offset within a tile (row, k-group)
__device__ __forceinline__ uint32_t goff(int row, int kg) {
    int p = row >> 1;
    int c = (kg ^ (p & 3)) | ((row & 1) << 2);
    return (uint32_t)((p * 8 + c) * 16);
}

// byte offset of element (m, j) inside a packed A buffer with K columns
__device__ __forceinline__ size_t packA(int m, int j, int K) {
    return ((size_t)(m >> 7) * (K >> 5) + (j >> 5)) * 16384
         + goff(m & 127, (j >> 3) & 3) + (j & 7) * 2;
}

// ---------------- weight transpose + split -> packed W blocks ---------------
__device__ __forceinline__ void transT_body(const float* __restrict__ in,
                                            char* __restrict__ op,
                                            int Kd, int Nd) {
    __shared__ float t[32][33];
    int n0 = blockIdx.x * 32, k0 = blockIdx.y * 32;
    int tx = threadIdx.x, ty = threadIdx.y;   // 32 x 8
#pragma unroll
    for (int i = 0; i < 32; i += 8)
        t[ty + i][tx] = in[(size_t)(k0 + ty + i) * Nd + n0 + tx];
    __syncthreads();
    int nkt = Kd >> 5;
    int kt  = k0 >> 5;
#pragma unroll
    for (int i = 0; i < 32; i += 8) {
        int n = n0 + ty + i;
        int nt = n / 96, r = n - nt * 96;
        float x = t[tx][ty + i];
        __nv_bfloat16 h, l; fsplit(x, h, l);
        size_t off = ((size_t)nt * nkt + kt) * 12288 + goff(r, (tx >> 3) & 3) + (tx & 7) * 2;
        *(__nv_bfloat16*)(op + off)        = h;
        *(__nv_bfloat16*)(op + off + 6144) = l;
    }
}

__global__ void transT(const float* __restrict__ in, char* __restrict__ op,
                       int Kd, int Nd) {
    transT_body(in, op, Kd, Nd);
}

__global__ void transT_hh(const float* __restrict__ p0, const float* __restrict__ p1,
                          const float* __restrict__ p2, const float* __restrict__ p3,
                          const float* __restrict__ p4, char* __restrict__ wp) {
    int z = blockIdx.z;
    int type = z / L_, layer = z % L_;
    const float* src = (type == 0) ? p0 : (type == 1) ? p1 : (type == 2) ? p2
                     : (type == 3) ? p3 : p4;
    size_t ooff = ((size_t)layer * WL_ +
        ((type == 0) ? OWK_ : (type == 1) ? OWV_ : (type == 2) ? OWR_
       : (type == 3) ? OWO_ : OFR_)) * 4;
    transT_body(src + (size_t)layer * H2_, wp + ooff, H_, H_);
}

__global__ void transT_rect(const float* __restrict__ p, char* __restrict__ wp,
                            int Kd, int Nd, size_t ooff_elem) {
    int layer = blockIdx.z;
    size_t o = ((size_t)layer * WL_ + ooff_elem) * 4;
    transT_body(p + (size_t)layer * Kd * Nd, wp + o, Kd, Nd);
}

// ---------------- LayerNorms -------------------------------------------------
__global__ void ln_kernel(const float* __restrict__ in,
                          const float* __restrict__ w,
                          const float* __restrict__ b,
                          float* __restrict__ out) {
    __shared__ float red[8];
    size_t base = (size_t)blockIdx.x * H_;
    float c[3];
    float s = 0.f, s2 = 0.f;
#pragma unroll
    for (int i = 0; i < 3; i++) {
        int j = threadIdx.x + i * 256;
        c[i] = in[base + j];
        s += c[i]; s2 += c[i] * c[i];
    }
    s  = bsum256(s,  red);
    s2 = bsum256(s2, red);
    float m = s / H_, v = s2 / H_ - m * m, rs = rsqrtf(v + EPS_);
#pragma unroll
    for (int i = 0; i < 3; i++) {
        int j = threadIdx.x + i * 256;
        out[base + j] = (c[i] - m) * rs * w[j] + b[j];
    }
}

__global__ void ln_split(const float* __restrict__ in,
                         const float* __restrict__ w,
                         const float* __restrict__ b,
                         char* __restrict__ op) {
    __shared__ float red[8];
    int row = blockIdx.x;
    size_t base = (size_t)row * H_;
    float c[3];
    float s = 0.f, s2 = 0.f;
#pragma unroll
    for (int i = 0; i < 3; i++) {
        int j = threadIdx.x + i * 256;
        c[i] = in[base + j];
        s += c[i]; s2 += c[i] * c[i];
    }
    s  = bsum256(s,  red);
    s2 = bsum256(s2, red);
    float m = s / H_, v = s2 / H_ - m * m, rs = rsqrtf(v + EPS_);
#pragma unroll
    for (int i = 0; i < 3; i++) {
        int j = threadIdx.x + i * 256;
        float x = (c[i] - m) * rs * w[j] + b[j];
        __nv_bfloat16 h, l; fsplit(x, h, l);
        size_t off = packA(row, j, H_);
        *(__nv_bfloat16*)(op + off)        = h;
        *(__nv_bfloat16*)(op + off + 8192) = l;
    }
}

// ---------------- LN + token-shift + lerp-mix -> packed ----------------------
__global__ void prep_mix(const float* __restrict__ hbuf,
                         const float* __restrict__ lnw, const float* __restrict__ lnb,
                         const float* __restrict__ mk,  const float* __restrict__ mv,
                         const float* __restrict__ mr,
                         char* __restrict__ xkp, char* __restrict__ xvp,
                         char* __restrict__ xrp) {
    __shared__ float red[8];
    int row = blockIdx.x;
    int t   = row % T_;
    const float* cur = hbuf + (size_t)row * H_;
    float c[3], p[3];
    float sc = 0.f, sc2 = 0.f, sp = 0.f, sp2 = 0.f;
#pragma unroll
    for (int i = 0; i < 3; i++) {
        int j = threadIdx.x + i * 256;
        c[i] = cur[j];
        sc += c[i]; sc2 += c[i] * c[i];
        p[i] = (t > 0) ? cur[j - H_] : 0.f;
        sp += p[i]; sp2 += p[i] * p[i];
    }
    sc  = bsum256(sc,  red);
    sc2 = bsum256(sc2, red);
    sp  = bsum256(sp,  red);
    sp2 = bsum256(sp2, red);
    float mc = sc / H_, vc = sc2 / H_ - mc * mc, rc = rsqrtf(vc + EPS_);
    float mp = sp / H_, vp = sp2 / H_ - mp * mp, rp = rsqrtf(vp + EPS_);
#pragma unroll
    for (int i = 0; i < 3; i++) {
        int j = threadIdx.x + i * 256;
        float w = lnw[j], bb = lnb[j];
        float hn = (c[i] - mc) * rc * w + bb;
        float sh = (t > 0) ? ((p[i] - mp) * rp * w + bb) : 0.f;
        size_t off = packA(row, j, H_);
        __nv_bfloat16 hh, ll;
        float k_ = mk[j];
        fsplit(hn * k_ + sh * (1.f - k_), hh, ll);
        *(__nv_bfloat16*)(xkp + off)        = hh;
        *(__nv_bfloat16*)(xkp + off + 8192) = ll;
        if (xvp) {
            float v_ = mv[j];
            fsplit(hn * v_ + sh * (1.f - v_), hh, ll);
            *(__nv_bfloat16*)(xvp + off)        = hh;
            *(__nv_bfloat16*)(xvp + off + 8192) = ll;
        }
        float r_ = mr[j];
        fsplit(hn * r_ + sh * (1.f - r_), hh, ll);
        *(__nv_bfloat16*)(xrp + off)        = hh;
        *(__nv_bfloat16*)(xrp + off + 8192) = ll;
    }
}

// ---------------- WKV scan -> packed ------------------------------------------
__global__ void wkv_kernel(const float* __restrict__ k,
                           const float* __restrict__ v,
                           const float* __restrict__ r,
                           const float* __restrict__ td,
                           const float* __restrict__ tf,
                           char* __restrict__ atp) {
    int c = blockIdx.x * blockDim.x + threadIdx.x;
    if (c >= B_ * H_) return;
    int b = c / H_, hh = c % H_;
    float w = -expf(td[hh]);
    float u = tf[hh];
    float num = 0.f, den = 0.f, mx = -1e38f;
    size_t base = (size_t)b * T_ * H_ + hh;
    int kt = hh >> 5, kg = (hh >> 3) & 3, byo = (hh & 7) * 2;
    for (int t = 0; t < T_; t++) {
        size_t idx = base + (size_t)t * H_;
        float kt_ = k[idx], vt = v[idx];
        float a  = kt_ + u;
        float mo = fmaxf(mx, a);
        float e1 = expf(mx - mo), e2 = expf(a - mo);
        float out = ((e1 * num + e2 * vt) / (e1 * den + e2)) * r[idx];
        __nv_bfloat16 oh, ol; fsplit(out, oh, ol);
        int row = b * T_ + t;
        size_t off = ((size_t)(row >> 7) * (H_ >> 5) + kt) * 16384
                   + goff(row & 127, kg) + byo;
        *(__nv_bfloat16*)(atp + off)        = oh;
        *(__nv_bfloat16*)(atp + off + 8192) = ol;
        float ms = fmaxf(mx + w, kt_);
        float f1 = expf(mx + w - ms), f2 = expf(kt_ - ms);
        num = f1 * num + f2 * vt;
        den = f1 * den + f2;
        mx  = ms;
    }
}

// ====================== bf16 3-term tensor-core GEMM ========================
// Tile 128x96. 224 threads = 6 compute warps (2x3, warp tile 64x32) + 1
// producer warp. K-tile 32, 4-stage cp.async.bulk pipeline, NO block syncs:
// full[s] (tx-based) gates consumers, free[s] (count=6) gates the producer.
// epi: 0 C=v, 1 C=sigmoid(v), 2 C+=v, 3 C+=aux*v, 4 Op=packed split(relu(v)^2)

#define TN_     96
#define AL_OFF  8192
#define BH_OFF  16384
#define BL_OFF  22528
#define STG_B   28672
#define NSTG    4
#define GEMM_SMEM (NSTG*STG_B)
#define GT_     224

__device__ __forceinline__ void mbar_init(uint32_t a, uint32_t cnt) {
    asm volatile("mbarrier.init.shared.b64 [%0], %1;" :: "r"(a), "r"(cnt) : "memory");
}
__device__ __forceinline__ void mbar_wait(uint32_t a, uint32_t parity) {
    asm volatile(
        "{ .reg .pred P;\n"
        "WL_%=: mbarrier.try_wait.parity.acquire.cta.shared::cta.b64 P, [%0], %1, 0x989680;\n"
        "@P bra WD_%=;\n"
        "bra WL_%=;\n"
        "WD_%=: }\n" :: "r"(a), "r"(parity) : "memory");
}
__device__ __forceinline__ void mbar_arrive(uint32_t a) {
    asm volatile("mbarrier.arrive.shared.b64 _, [%0];" :: "r"(a) : "memory");
}
__device__ __forceinline__ void mbar_expect_tx(uint32_t a, uint32_t bytes) {
    asm volatile("mbarrier.arrive.expect_tx.shared.b64 _, [%0], %1;"
                 :: "r"(a), "r"(bytes) : "memory");
}
__device__ __forceinline__ void bulk_g2s(uint32_t dst, const void* src,
                                         uint32_t bytes, uint32_t mbar) {
    asm volatile(
        "cp.async.bulk.shared::cta.global.mbarrier::complete_tx::bytes [%0], [%1], %2, [%3];"
        :: "r"(dst), "l"(src), "r"(bytes), "r"(mbar) : "memory");
}
__device__ __forceinline__ void ldsm4(uint32_t r[4], uint32_t a) {
    asm volatile("ldmatrix.sync.aligned.m8n8.x4.shared.b16 {%0,%1,%2,%3}, [%4];\n"
                 : "=r"(r[0]), "=r"(r[1]), "=r"(r[2]), "=r"(r[3]) : "r"(a));
}
__device__ __forceinline__ void mma16816(float c[4], const uint32_t a[4],
                                         uint32_t b0, uint32_t b1) {
    asm volatile(
        "mma.sync.aligned.m16n8k16.row.col.f32.bf16.bf16.f32 "
        "{%0,%1,%2,%3}, {%4,%5,%6,%7}, {%8,%9}, {%0,%1,%2,%3};\n"
        : "+f"(c[0]), "+f"(c[1]), "+f"(c[2]), "+f"(c[3])
        : "r"(a[0]), "r"(a[1]), "r"(a[2]), "r"(a[3]), "r"(b0), "r"(b1));
}

__device__ __forceinline__ void tc_body(
    const char* __restrict__ Ap, const char* __restrict__ Bp,
    float* __restrict__ C, const float* __restrict__ aux,
    char* __restrict__ Op,
    int epi, int N, int K, int bm, int bnt, uint8_t* sm8) {

    __shared__ uint64_t s_mb[2 * NSTG];   // full[0..3], free[4..7]
    uint32_t sb  = (uint32_t)__cvta_generic_to_shared(sm8);
    uint32_t mbF = (uint32_t)__cvta_generic_to_shared(&s_mb[0]);
    uint32_t mbE = (uint32_t)__cvta_generic_to_shared(&s_mb[NSTG]);

    int tid = threadIdx.x;
    int l   = tid & 31;
    int w   = tid >> 5;        // 0..6
    int bn  = bnt * TN_;
    int nkt = K >> 5;

    if (tid == 0) {
#pragma unroll
        for (int s = 0; s < NSTG; s++) { mbar_init(mbF + 8*s, 1); mbar_init(mbE + 8*s, 6); }
    }
    __syncthreads();

    if (w == 6) {
        // ---------------- producer warp (lane 0 only) ----------------
        if (l == 0) {
#pragma unroll 1
            for (int i = 0; i < nkt; i++) {
                int s = i & (NSTG - 1);
                if (i >= NSTG) mbar_wait(mbE + 8*s, ((i >> 2) - 1) & 1);
                mbar_expect_tx(mbF + 8*s, STG_B);
                uint32_t st = sb + s * STG_B;
                size_t ab = ((size_t)(bm >> 7) * nkt + i) * 16384;
                size_t bb = ((size_t)bnt * nkt + i) * 12288;
                bulk_g2s(st,          Ap + ab, 16384, mbF + 8*s);
                bulk_g2s(st + BH_OFF, Bp + bb, 12288, mbF + 8*s);
            }
        }
        return;
    }

    // ---------------- compute warps ----------------
    int wm  = w / 3;           // 0..1
    int wn  = w % 3;           // 0..2
    int sub = l >> 3;

    float acc[4][4][4];
#pragma unroll
    for (int mi = 0; mi < 4; mi++)
#pragma unroll
        for (int ni = 0; ni < 4; ni++)
#pragma unroll
            for (int q = 0; q < 4; q++) acc[mi][ni][q] = 0.f;

    int arow0 = wm * 64 + (l & 7) + ((sub & 1) << 3);
    int brow0 = wn * 32 + (l & 7) + ((sub >> 1) << 3);
    int akg_ = (sub >> 1);
    int bkg_ = (sub & 1);

#pragma unroll 1
    for (int i = 0; i < nkt; i++) {
        int s = i & (NSTG - 1);
        mbar_wait(mbF + 8*s, (i >> 2) & 1);
        uint32_t st = sb + s * STG_B;

#pragma unroll
        for (int ks = 0; ks < 2; ks++) {
            int akg = ks * 2 + akg_;
            int bkg = ks * 2 + bkg_;

            uint32_t ah[4][4], bh[2][4], xl[4][4], yl[2][4];
#pragma unroll
            for (int mi = 0; mi < 4; mi++) ldsm4(ah[mi], st + goff(arow0 + mi * 16, akg));
#pragma unroll
            for (int g = 0; g < 2; g++)    ldsm4(bh[g], st + BH_OFF + goff(brow0 + g * 16, bkg));
#pragma unroll
            for (int mi = 0; mi < 4; mi++)
#pragma unroll
                for (int ni = 0; ni < 4; ni++) {
                    int g = ni >> 1, o = (ni & 1) * 2;
                    mma16816(acc[mi][ni], ah[mi], bh[g][o], bh[g][o + 1]);
                }
#pragma unroll
            for (int mi = 0; mi < 4; mi++) ldsm4(xl[mi], st + AL_OFF + goff(arow0 + mi * 16, akg));
#pragma unroll
            for (int mi = 0; mi < 4; mi++)
#pragma unroll
                for (int ni = 0; ni < 4; ni++) {
                    int g = ni >> 1, o = (ni & 1) * 2;
                    mma16816(acc[mi][ni], xl[mi], bh[g][o], bh[g][o + 1]);
                }
#pragma unroll
            for (int g = 0; g < 2; g++)    ldsm4(yl[g], st + BL_OFF + goff(brow0 + g * 16, bkg));
#pragma unroll
            for (int mi = 0; mi < 4; mi++)
#pragma unroll
                for (int ni = 0; ni < 4; ni++) {
                    int g = ni >> 1, o = (ni & 1) * 2;
                    mma16816(acc[mi][ni], ah[mi], yl[g][o], yl[g][o + 1]);
                }
        }
        if (l == 0) mbar_arrive(mbE + 8*s);
    }

    // ---- epilogue ----
#pragma unroll
    for (int mi = 0; mi < 4; mi++) {
#pragma unroll
        for (int ni = 0; ni < 4; ni++) {
            int r0 = bm + wm * 64 + mi * 16 + (l >> 2);
            int c0 = bn + wn * 32 + ni * 8 + (l & 3) * 2;
#pragma unroll
            for (int q = 0; q < 4; q++) {
                int rr = r0 + (q >> 1) * 8;
                int cc = c0 + (q & 1);
                float v = acc[mi][ni][q];
                if (epi == 4) {
                    float qq = fmaxf(v, 0.f); qq = qq * qq;
                    __nv_bfloat16 hh, ll; fsplit(qq, hh, ll);
                    size_t off = packA(rr, cc, N);
                    *(__nv_bfloat16*)(Op + off)        = hh;
                    *(__nv_bfloat16*)(Op + off + 8192) = ll;
                } else {
                    size_t idx = (size_t)rr * N + cc;
                    if (epi == 0)      C[idx] = v;
                    else if (epi == 1) C[idx] = 1.f / (1.f + expf(-v));
                    else if (epi == 2) C[idx] += v;
                    else               C[idx] += aux[idx] * v;
                }
            }
        }
    }
}

// ---- kernel wrappers ----
__global__ __launch_bounds__(GT_, 2) void tgemm(
    const char* __restrict__ Ap, const char* __restrict__ Bp,
    float* C, const float* aux, char* Op, int epi, int N, int K) {
    extern __shared__ __align__(16) uint8_t sm8[];
    tc_body(Ap, Bp, C, aux, Op, epi, N, K, blockIdx.y * 128, blockIdx.x, sm8);
}

// batched k/v/r: grid (8, 32, 3)
__global__ __launch_bounds__(GT_, 2) void tgemm_kvr(const char* __restrict__ wp) {
    extern __shared__ __align__(16) uint8_t sm8[];
    int z = blockIdx.z;
    const char* Ap = (z == 0) ? g_xkp : (z == 1) ? g_xvp : g_xrp;
    size_t wo = ((z == 0) ? (size_t)OWK_ : (z == 1) ? (size_t)OWV_ : (size_t)OWR_) * 4;
    float* C = (z == 0) ? g_k : (z == 1) ? g_v : g_r;
    tc_body(Ap, wp + wo, C, nullptr, nullptr, (z == 2) ? 1 : 0, H_, H_,
            blockIdx.y * 128, blockIdx.x, sm8);
}

// batched Fk (x<32) + Fr (x>=32): grid (40, 32)
__global__ __launch_bounds__(GT_, 2) void tgemm_ff(const char* __restrict__ wp) {
    extern __shared__ __align__(16) uint8_t sm8[];
    int bx = blockIdx.x;
    if (bx < 32)
        tc_body(g_xkp, wp + (size_t)OFK_ * 4, nullptr, nullptr, g_kfp,
                4, FF_, H_, blockIdx.y * 128, bx, sm8);
    else
        tc_body(g_xrp, wp + (size_t)OFR_ * 4, g_r, nullptr, nullptr,
                1, H_, H_, blockIdx.y * 128, bx - 32, sm8);
}

// ---------------- host orchestration -----------------------------------------
extern "C" void kernel_launch(void* const* d_in, const int* in_sizes, int n_in,
                              void* d_out, int out_size) {
    (void)in_sizes; (void)n_in; (void)out_size;
    const float* x     = (const float*)d_in[0];
    const float* prew  = (const float*)d_in[1];
    const float* preb  = (const float*)d_in[2];
    const float* ln1w  = (const float*)d_in[3];
    const float* ln1b  = (const float*)d_in[4];
    const float* ln2w  = (const float*)d_in[5];
    const float* ln2b  = (const float*)d_in[6];
    const float* td    = (const float*)d_in[7];
    const float* tf    = (const float*)d_in[8];
    const float* amk   = (const float*)d_in[9];
    const float* amv   = (const float*)d_in[10];
    const float* amr   = (const float*)d_in[11];
    const float* Wk    = (const float*)d_in[12];
    const float* Wv    = (const float*)d_in[13];
    const float* Wr    = (const float*)d_in[14];
    const float* Wo    = (const float*)d_in[15];
    const float* fmk   = (const float*)d_in[16];
    const float* fmr   = (const float*)d_in[17];
    const float* Fk    = (const float*)d_in[18];
    const float* Fv    = (const float*)d_in[19];
    const float* Fr    = (const float*)d_in[20];
    const float* lnow  = (const float*)d_in[21];
    const float* lnob  = (const float*)d_in[22];
    const float* headw = (const float*)d_in[23];

    float *h, *k, *v, *r;
    char *wp, *xkp, *xvp, *xrp, *atp, *kfp;
    cudaGetSymbolAddress((void**)&h,   g_h);
    cudaGetSymbolAddress((void**)&k,   g_k);
    cudaGetSymbolAddress((void**)&v,   g_v);
    cudaGetSymbolAddress((void**)&r,   g_r);
    cudaGetSymbolAddress((void**)&wp,  g_wp);
    cudaGetSymbolAddress((void**)&xkp, g_xkp);
    cudaGetSymbolAddress((void**)&xvp, g_xvp);
    cudaGetSymbolAddress((void**)&xrp, g_xrp);
    cudaGetSymbolAddress((void**)&atp, g_atp);
    cudaGetSymbolAddress((void**)&kfp, g_kfp);

    cudaFuncSetAttribute(tgemm,     cudaFuncAttributeMaxDynamicSharedMemorySize, GEMM_SMEM);
    cudaFuncSetAttribute(tgemm_kvr, cudaFuncAttributeMaxDynamicSharedMemorySize, GEMM_SMEM);
    cudaFuncSetAttribute(tgemm_ff,  cudaFuncAttributeMaxDynamicSharedMemorySize, GEMM_SMEM);

    dim3 blk(256);
    dim3 gblk(GT_);
    dim3 tb(32, 8);
    dim3 gHHz(H_ / 32, H_ / 32, 5 * L_);
    dim3 gHFz(FF_ / 32, H_ / 32, L_);
    dim3 gFHz(H_ / 32, FF_ / 32, L_);
    dim3 gHH(H_ / 32, H_ / 32);
    dim3 gH(H_ / TN_,  BT_ / 128);        // (8, 32)
    dim3 gKVR(H_ / TN_, BT_ / 128, 3);    // (8, 32, 3)
    dim3 gFF(FF_ / TN_ + H_ / TN_, BT_ / 128);  // (40, 32)

    ln_kernel<<<BT_, blk>>>(x, prew, preb, h);
    transT_hh<<<gHHz, tb>>>(Wk, Wv, Wr, Wo, Fr, wp);
    transT_rect<<<gHFz, tb>>>(Fk, wp, H_, FF_, (size_t)OFK_);
    transT_rect<<<gFHz, tb>>>(Fv, wp, FF_, H_, (size_t)OFV_);

    for (int i = 0; i < L_; i++) {
        size_t oH  = (size_t)i * H_;
        size_t wb4 = (size_t)i * WL_ * 4;

        // --- time mixing ---
        prep_mix<<<BT_, blk>>>(h, ln1w + oH, ln1b + oH, amk + oH, amv + oH, amr + oH,
                               xkp, xvp, xrp);
        tgemm_kvr<<<gKVR, gblk, GEMM_SMEM>>>(wp + wb4);
        wkv_kernel<<<(B_ * H_ + 255) / 256, blk>>>(k, v, r, td + oH, tf + oH, atp);
        tgemm<<<gH, gblk, GEMM_SMEM>>>(atp, wp + wb4 + (size_t)OWO_ * 4,
                                       h, nullptr, nullptr, 2, H_, H_);

        // --- channel mixing ---
        prep_mix<<<BT_, blk>>>(h, ln2w + oH, ln2b + oH, fmk + oH, nullptr, fmr + oH,
                               xkp, nullptr, xrp);
        tgemm_ff<<<gFF, gblk, GEMM_SMEM>>>(wp + wb4);
        tgemm<<<gH, gblk, GEMM_SMEM>>>(kfp, wp + wb4 + (size_t)OFV_ * 4,
                                       h, r, nullptr, 3, H_, FF_);
    }

    size_t hb4 = (size_t)L_ * WL_ * 4;
    transT<<<gHH, tb>>>(headw, wp + hb4, H_, H_);
    ln_split<<<BT_, blk>>>(h, lnow, lnob, xkp);
    tgemm<<<gH, gblk, GEMM_SMEM>>>(xkp, wp + hb4,
                                   (float*)d_out, nullptr, nullptr, 0, H_, H_);
}

// round 15
// speedup vs baseline: 1.0958x; 1.0958x over previous
#include <cuda_runtime.h>
#include <cuda_bf16.h>
#include <cstdint>

#define B_   8
#define T_   512
#define H_   768
#define L_   12
#define FF_  3072
#define BT_  (B_*T_)
#define EPS_ 1e-5f

#define H2_  (H_*H_)
#define HFF_ (H_*FF_)
#define WL_  (5*H2_ + 2*HFF_)
#define WTOT_ ((size_t)L_*WL_ + H2_)

#define OWK_ 0
#define OWV_ (1*H2_)
#define OWR_ (2*H2_)
#define OWO_ (3*H2_)
#define OFR_ (4*H2_)
#define OFK_ (5*H2_)
#define OFV_ (5*H2_ + HFF_)

// ---------------- scratch (static device globals; no allocation) ----------
__device__ float g_h[BT_*H_];
__device__ float g_k[BT_*H_];
__device__ float g_v[BT_*H_];
__device__ float g_r[BT_*H_];

// packed, pre-swizzled operand buffers (hi/lo halves per block)
// A blocks: 128 rows x 32 cols, hi 8KB + lo 8KB = 16KB per block
// W blocks:  96 rows x 32 cols, hi 6KB + lo 6KB = 12KB per block
__device__ __align__(1024) char g_wp [WTOT_*4];
__device__ __align__(1024) char g_xkp[(size_t)BT_*H_*4];
__device__ __align__(1024) char g_xvp[(size_t)BT_*H_*4];
__device__ __align__(1024) char g_xrp[(size_t)BT_*H_*4];
__device__ __align__(1024) char g_atp[(size_t)BT_*H_*4];
__device__ __align__(1024) char g_kfp[(size_t)BT_*FF_*4];

// ---------------- helpers ---------------------------------------------------
__device__ __forceinline__ void fsplit(float x, __nv_bfloat16& h, __nv_bfloat16& l) {
    h = __float2bfloat16_rn(x);
    l = __float2bfloat16_rn(x - __bfloat162float(h));
}

__device__ __forceinline__ float bsum256(float val, float* red) {
    int lane = threadIdx.x & 31;
    int w    = threadIdx.x >> 5;
#pragma unroll
    for (int o = 16; o; o >>= 1) val += __shfl_xor_sync(0xffffffffu, val, o);
    __syncthreads();
    if (lane == 0) red[w] = val;
    __syncthreads();
    float s = 0.f;
#pragma unroll
    for (int i = 0; i < 8; i++) s += red[i];
    return s;
}

// swizzled 16B-chunk offset within a tile (row, k-group)
__device__ __forceinline__ uint32_t goff(int row, int kg) {
    int p = row >> 1;
    int c = (kg ^ (p & 3)) | ((row & 1) << 2);
    return (uint32_t)((p * 8 + c) * 16);
}

// byte offset of element (m, j) inside a packed A buffer with K columns
__device__ __forceinline__ size_t packA(int m, int j, int K) {
    return ((size_t)(m >> 7) * (K >> 5) + (j >> 5)) * 16384
         + goff(m & 127, (j >> 3) & 3) + (j & 7) * 2;
}

// ---------------- weight transpose + split -> packed W blocks ---------------
__device__ __forceinline__ void transT_body(const float* __restrict__ in,
                                            char* __restrict__ op,
                                            int Kd, int Nd) {
    __shared__ float t[32][33];
    int n0 = blockIdx.x * 32, k0 = blockIdx.y * 32;
    int tx = threadIdx.x, ty = threadIdx.y;   // 32 x 8
#pragma unroll
    for (int i = 0; i < 32; i += 8)
        t[ty + i][tx] = in[(size_t)(k0 + ty + i) * Nd + n0 + tx];
    __syncthreads();
    int nkt = Kd >> 5;
    int kt  = k0 >> 5;
#pragma unroll
    for (int i = 0; i < 32; i += 8) {
        int n = n0 + ty + i;
        int nt = n / 96, r = n - nt * 96;
        float x = t[tx][ty + i];
        __nv_bfloat16 h, l; fsplit(x, h, l);
        size_t off = ((size_t)nt * nkt + kt) * 12288 + goff(r, (tx >> 3) & 3) + (tx & 7) * 2;
        *(__nv_bfloat16*)(op + off)        = h;
        *(__nv_bfloat16*)(op + off + 6144) = l;
    }
}

__global__ void transT(const float* __restrict__ in, char* __restrict__ op,
                       int Kd, int Nd) {
    transT_body(in, op, Kd, Nd);
}

__global__ void transT_hh(const float* __restrict__ p0, const float* __restrict__ p1,
                          const float* __restrict__ p2, const float* __restrict__ p3,
                          const float* __restrict__ p4, char* __restrict__ wp) {
    int z = blockIdx.z;
    int type = z / L_, layer = z % L_;
    const float* src = (type == 0) ? p0 : (type == 1) ? p1 : (type == 2) ? p2
                     : (type == 3) ? p3 : p4;
    size_t ooff = ((size_t)layer * WL_ +
        ((type == 0) ? OWK_ : (type == 1) ? OWV_ : (type == 2) ? OWR_
       : (type == 3) ? OWO_ : OFR_)) * 4;
    transT_body(src + (size_t)layer * H2_, wp + ooff, H_, H_);
}

__global__ void transT_rect(const float* __restrict__ p, char* __restrict__ wp,
                            int Kd, int Nd, size_t ooff_elem) {
    int layer = blockIdx.z;
    size_t o = ((size_t)layer * WL_ + ooff_elem) * 4;
    transT_body(p + (size_t)layer * Kd * Nd, wp + o, Kd, Nd);
}

// ---------------- LayerNorms -------------------------------------------------
__global__ void ln_kernel(const float* __restrict__ in,
                          const float* __restrict__ w,
                          const float* __restrict__ b,
                          float* __restrict__ out) {
    __shared__ float red[8];
    size_t base = (size_t)blockIdx.x * H_;
    float c[3];
    float s = 0.f, s2 = 0.f;
#pragma unroll
    for (int i = 0; i < 3; i++) {
        int j = threadIdx.x + i * 256;
        c[i] = in[base + j];
        s += c[i]; s2 += c[i] * c[i];
    }
    s  = bsum256(s,  red);
    s2 = bsum256(s2, red);
    float m = s / H_, v = s2 / H_ - m * m, rs = rsqrtf(v + EPS_);
#pragma unroll
    for (int i = 0; i < 3; i++) {
        int j = threadIdx.x + i * 256;
        out[base + j] = (c[i] - m) * rs * w[j] + b[j];
    }
}

__global__ void ln_split(const float* __restrict__ in,
                         const float* __restrict__ w,
                         const float* __restrict__ b,
                         char* __restrict__ op) {
    __shared__ float red[8];
    int row = blockIdx.x;
    size_t base = (size_t)row * H_;
    float c[3];
    float s = 0.f, s2 = 0.f;
#pragma unroll
    for (int i = 0; i < 3; i++) {
        int j = threadIdx.x + i * 256;
        c[i] = in[base + j];
        s += c[i]; s2 += c[i] * c[i];
    }
    s  = bsum256(s,  red);
    s2 = bsum256(s2, red);
    float m = s / H_, v = s2 / H_ - m * m, rs = rsqrtf(v + EPS_);
#pragma unroll
    for (int i = 0; i < 3; i++) {
        int j = threadIdx.x + i * 256;
        float x = (c[i] - m) * rs * w[j] + b[j];
        __nv_bfloat16 h, l; fsplit(x, h, l);
        size_t off = packA(row, j, H_);
        *(__nv_bfloat16*)(op + off)        = h;
        *(__nv_bfloat16*)(op + off + 8192) = l;
    }
}

// ---------------- LN + token-shift + lerp-mix -> packed ----------------------
__global__ void prep_mix(const float* __restrict__ hbuf,
                         const float* __restrict__ lnw, const float* __restrict__ lnb,
                         const float* __restrict__ mk,  const float* __restrict__ mv,
                         const float* __restrict__ mr,
                         char* __restrict__ xkp, char* __restrict__ xvp,
                         char* __restrict__ xrp) {
    __shared__ float red[8];
    int row = blockIdx.x;
    int t   = row % T_;
    const float* cur = hbuf + (size_t)row * H_;
    float c[3], p[3];
    float sc = 0.f, sc2 = 0.f, sp = 0.f, sp2 = 0.f;
#pragma unroll
    for (int i = 0; i < 3; i++) {
        int j = threadIdx.x + i * 256;
        c[i] = cur[j];
        sc += c[i]; sc2 += c[i] * c[i];
        p[i] = (t > 0) ? cur[j - H_] : 0.f;
        sp += p[i]; sp2 += p[i] * p[i];
    }
    sc  = bsum256(sc,  red);
    sc2 = bsum256(sc2, red);
    sp  = bsum256(sp,  red);
    sp2 = bsum256(sp2, red);
    float mc = sc / H_, vc = sc2 / H_ - mc * mc, rc = rsqrtf(vc + EPS_);
    float mp = sp / H_, vp = sp2 / H_ - mp * mp, rp = rsqrtf(vp + EPS_);
#pragma unroll
    for (int i = 0; i < 3; i++) {
        int j = threadIdx.x + i * 256;
        float w = lnw[j], bb = lnb[j];
        float hn = (c[i] - mc) * rc * w + bb;
        float sh = (t > 0) ? ((p[i] - mp) * rp * w + bb) : 0.f;
        size_t off = packA(row, j, H_);
        __nv_bfloat16 hh, ll;
        float k_ = mk[j];
        fsplit(hn * k_ + sh * (1.f - k_), hh, ll);
        *(__nv_bfloat16*)(xkp + off)        = hh;
        *(__nv_bfloat16*)(xkp + off + 8192) = ll;
        if (xvp) {
            float v_ = mv[j];
            fsplit(hn * v_ + sh * (1.f - v_), hh, ll);
            *(__nv_bfloat16*)(xvp + off)        = hh;
            *(__nv_bfloat16*)(xvp + off + 8192) = ll;
        }
        float r_ = mr[j];
        fsplit(hn * r_ + sh * (1.f - r_), hh, ll);
        *(__nv_bfloat16*)(xrp + off)        = hh;
        *(__nv_bfloat16*)(xrp + off + 8192) = ll;
    }
}

// ---------------- WKV scan -> packed ------------------------------------------
__global__ void wkv_kernel(const float* __restrict__ k,
                           const float* __restrict__ v,
                           const float* __restrict__ r,
                           const float* __restrict__ td,
                           const float* __restrict__ tf,
                           char* __restrict__ atp) {
    int c = blockIdx.x * blockDim.x + threadIdx.x;
    if (c >= B_ * H_) return;
    int b = c / H_, hh = c % H_;
    float w = -expf(td[hh]);
    float u = tf[hh];
    float num = 0.f, den = 0.f, mx = -1e38f;
    size_t base = (size_t)b * T_ * H_ + hh;
    int kt = hh >> 5, kg = (hh >> 3) & 3, byo = (hh & 7) * 2;
    for (int t = 0; t < T_; t++) {
        size_t idx = base + (size_t)t * H_;
        float kt_ = k[idx], vt = v[idx];
        float a  = kt_ + u;
        float mo = fmaxf(mx, a);
        float e1 = expf(mx - mo), e2 = expf(a - mo);
        float out = ((e1 * num + e2 * vt) / (e1 * den + e2)) * r[idx];
        __nv_bfloat16 oh, ol; fsplit(out, oh, ol);
        int row = b * T_ + t;
        size_t off = ((size_t)(row >> 7) * (H_ >> 5) + kt) * 16384
                   + goff(row & 127, kg) + byo;
        *(__nv_bfloat16*)(atp + off)        = oh;
        *(__nv_bfloat16*)(atp + off + 8192) = ol;
        float ms = fmaxf(mx + w, kt_);
        float f1 = expf(mx + w - ms), f2 = expf(kt_ - ms);
        num = f1 * num + f2 * vt;
        den = f1 * den + f2;
        mx  = ms;
    }
}

// ====================== bf16 3-term tensor-core GEMM ========================
// Tile 128x96, 256 threads = 8 warps (2x4), warp tile 64x24 -> perfectly
// balanced 2 warps/SMSP per CTA. K-tile 32, 4-stage cp.async.bulk pipeline,
// block-sync structure (R13 skeleton).
// epi: 0 C=v, 1 C=sigmoid(v), 2 C+=v, 3 C+=aux*v, 4 Op=packed split(relu(v)^2)

#define TN_     96
#define AL_OFF  8192
#define BH_OFF  16384
#define BL_OFF  22528
#define STG_B   28672
#define NSTG    4
#define GEMM_SMEM (NSTG*STG_B)
#define GT_     256

__device__ __forceinline__ void mbar_init(uint32_t a, uint32_t cnt) {
    asm volatile("mbarrier.init.shared.b64 [%0], %1;" :: "r"(a), "r"(cnt) : "memory");
}
__device__ __forceinline__ void mbar_wait(uint32_t a, uint32_t parity) {
    asm volatile(
        "{ .reg .pred P;\n"
        "WL_%=: mbarrier.try_wait.parity.acquire.cta.shared::cta.b64 P, [%0], %1, 0x989680;\n"
        "@P bra WD_%=;\n"
        "bra WL_%=;\n"
        "WD_%=: }\n" :: "r"(a), "r"(parity) : "memory");
}
__device__ __forceinline__ void mbar_expect_tx(uint32_t a, uint32_t bytes) {
    asm volatile("mbarrier.arrive.expect_tx.shared.b64 _, [%0], %1;"
                 :: "r"(a), "r"(bytes) : "memory");
}
__device__ __forceinline__ void bulk_g2s(uint32_t dst, const void* src,
                                         uint32_t bytes, uint32_t mbar) {
    asm volatile(
        "cp.async.bulk.shared::cta.global.mbarrier::complete_tx::bytes [%0], [%1], %2, [%3];"
        :: "r"(dst), "l"(src), "r"(bytes), "r"(mbar) : "memory");
}
__device__ __forceinline__ void ldsm4(uint32_t r[4], uint32_t a) {
    asm volatile("ldmatrix.sync.aligned.m8n8.x4.shared.b16 {%0,%1,%2,%3}, [%4];\n"
                 : "=r"(r[0]), "=r"(r[1]), "=r"(r[2]), "=r"(r[3]) : "r"(a));
}
__device__ __forceinline__ void ldsm2(uint32_t r[2], uint32_t a) {
    asm volatile("ldmatrix.sync.aligned.m8n8.x2.shared.b16 {%0,%1}, [%2];\n"
                 : "=r"(r[0]), "=r"(r[1]) : "r"(a));
}
__device__ __forceinline__ void mma16816(float c[4], const uint32_t a[4],
                                         uint32_t b0, uint32_t b1) {
    asm volatile(
        "mma.sync.aligned.m16n8k16.row.col.f32.bf16.bf16.f32 "
        "{%0,%1,%2,%3}, {%4,%5,%6,%7}, {%8,%9}, {%0,%1,%2,%3};\n"
        : "+f"(c[0]), "+f"(c[1]), "+f"(c[2]), "+f"(c[3])
        : "r"(a[0]), "r"(a[1]), "r"(a[2]), "r"(a[3]), "r"(b0), "r"(b1));
}

__device__ __forceinline__ void tc_body(
    const char* __restrict__ Ap, const char* __restrict__ Bp,
    float* __restrict__ C, const float* __restrict__ aux,
    char* __restrict__ Op,
    int epi, int N, int K, int bm, int bnt, uint8_t* sm8) {

    __shared__ uint64_t s_mb[NSTG];
    uint32_t sb = (uint32_t)__cvta_generic_to_shared(sm8);
    uint32_t mb = (uint32_t)__cvta_generic_to_shared(&s_mb[0]);

    int tid = threadIdx.x;
    int l   = tid & 31;
    int w   = tid >> 5;        // 0..7
    int wm  = w >> 2;          // 0..1
    int wn  = w & 3;           // 0..3
    int sub = l >> 3;
    int bn  = bnt * TN_;
    int nkt = K >> 5;

    if (tid == 0) {
#pragma unroll
        for (int s = 0; s < NSTG; s++) mbar_init(mb + 8*s, 1);
    }
    __syncthreads();

    auto issue = [&](int i) {
        int s = i & (NSTG - 1);
        uint32_t st = sb + s * STG_B;
        mbar_expect_tx(mb + 8*s, STG_B);
        size_t ab = ((size_t)(bm >> 7) * nkt + i) * 16384;
        size_t bb = ((size_t)bnt * nkt + i) * 12288;
        bulk_g2s(st,          Ap + ab, 16384, mb + 8*s);
        bulk_g2s(st + BH_OFF, Bp + bb, 12288, mb + 8*s);
    };
    if (tid == 0) { issue(0); issue(1); issue(2); issue(3); }

    float acc[4][3][4];
#pragma unroll
    for (int mi = 0; mi < 4; mi++)
#pragma unroll
        for (int ni = 0; ni < 3; ni++)
#pragma unroll
            for (int q = 0; q < 4; q++) acc[mi][ni][q] = 0.f;

    int arow0 = wm * 64 + (l & 7) + ((sub & 1) << 3);
    int brow0 = wn * 24 + (l & 7) + ((sub >> 1) << 3);   // rows 0..15 of warp's 24
    int brow2 = wn * 24 + 16 + (l & 7);                  // rows 16..23 (x2)
    int akg_  = (sub >> 1);
    int bkg_  = (sub & 1);
    int bkg2_ = (l >> 3) & 1;                            // x2: lanes 0-15 pick kg half

#pragma unroll 1
    for (int i = 0; i < nkt; i++) {
        int s = i & (NSTG - 1);
        mbar_wait(mb + 8*s, (i >> 2) & 1);
        uint32_t st = sb + s * STG_B;

#pragma unroll
        for (int ks = 0; ks < 2; ks++) {
            int akg  = ks * 2 + akg_;
            int bkg  = ks * 2 + bkg_;
            int bkg2 = ks * 2 + bkg2_;

            uint32_t ah[4][4], bh[4], bx[2], al[4][4], blh[4], blx[2];
#pragma unroll
            for (int mi = 0; mi < 4; mi++) ldsm4(ah[mi], st + goff(arow0 + mi * 16, akg));
            ldsm4(bh, st + BH_OFF + goff(brow0, bkg));
            ldsm2(bx, st + BH_OFF + goff(brow2, bkg2));

            // pass 1: ah * bh
#pragma unroll
            for (int mi = 0; mi < 4; mi++) {
                mma16816(acc[mi][0], ah[mi], bh[0], bh[1]);
                mma16816(acc[mi][1], ah[mi], bh[2], bh[3]);
                mma16816(acc[mi][2], ah[mi], bx[0], bx[1]);
            }
            // pass 2: al * bh
#pragma unroll
            for (int mi = 0; mi < 4; mi++) ldsm4(al[mi], st + AL_OFF + goff(arow0 + mi * 16, akg));
#pragma unroll
            for (int mi = 0; mi < 4; mi++) {
                mma16816(acc[mi][0], al[mi], bh[0], bh[1]);
                mma16816(acc[mi][1], al[mi], bh[2], bh[3]);
                mma16816(acc[mi][2], al[mi], bx[0], bx[1]);
            }
            // pass 3: ah * bl
            ldsm4(blh, st + BL_OFF + goff(brow0, bkg));
            ldsm2(blx, st + BL_OFF + goff(brow2, bkg2));
#pragma unroll
            for (int mi = 0; mi < 4; mi++) {
                mma16816(acc[mi][0], ah[mi], blh[0], blh[1]);
                mma16816(acc[mi][1], ah[mi], blh[2], blh[3]);
                mma16816(acc[mi][2], ah[mi], blx[0], blx[1]);
            }
        }

        __syncthreads();
        if (tid == 0 && i + NSTG < nkt) issue(i + NSTG);
    }

    // ---- epilogue ----
#pragma unroll
    for (int mi = 0; mi < 4; mi++) {
#pragma unroll
        for (int ni = 0; ni < 3; ni++) {
            int r0 = bm + wm * 64 + mi * 16 + (l >> 2);
            int c0 = bn + wn * 24 + ni * 8 + (l & 3) * 2;
#pragma unroll
            for (int q = 0; q < 4; q++) {
                int rr = r0 + (q >> 1) * 8;
                int cc = c0 + (q & 1);
                float v = acc[mi][ni][q];
                if (epi == 4) {
                    float qq = fmaxf(v, 0.f); qq = qq * qq;
                    __nv_bfloat16 hh, ll; fsplit(qq, hh, ll);
                    size_t off = packA(rr, cc, N);
                    *(__nv_bfloat16*)(Op + off)        = hh;
                    *(__nv_bfloat16*)(Op + off + 8192) = ll;
                } else {
                    size_t idx = (size_t)rr * N + cc;
                    if (epi == 0)      C[idx] = v;
                    else if (epi == 1) C[idx] = 1.f / (1.f + expf(-v));
                    else if (epi == 2) C[idx] += v;
                    else               C[idx] += aux[idx] * v;
                }
            }
        }
    }
}

// ---- kernel wrappers ----
__global__ __launch_bounds__(GT_, 2) void tgemm(
    const char* __restrict__ Ap, const char* __restrict__ Bp,
    float* C, const float* aux, char* Op, int epi, int N, int K) {
    extern __shared__ __align__(16) uint8_t sm8[];
    tc_body(Ap, Bp, C, aux, Op, epi, N, K, blockIdx.y * 128, blockIdx.x, sm8);
}

// batched k/v/r: grid (8, 32, 3)
__global__ __launch_bounds__(GT_, 2) void tgemm_kvr(const char* __restrict__ wp) {
    extern __shared__ __align__(16) uint8_t sm8[];
    int z = blockIdx.z;
    const char* Ap = (z == 0) ? g_xkp : (z == 1) ? g_xvp : g_xrp;
    size_t wo = ((z == 0) ? (size_t)OWK_ : (z == 1) ? (size_t)OWV_ : (size_t)OWR_) * 4;
    float* C = (z == 0) ? g_k : (z == 1) ? g_v : g_r;
    tc_body(Ap, wp + wo, C, nullptr, nullptr, (z == 2) ? 1 : 0, H_, H_,
            blockIdx.y * 128, blockIdx.x, sm8);
}

// batched Fk (x<32) + Fr (x>=32): grid (40, 32)
__global__ __launch_bounds__(GT_, 2) void tgemm_ff(const char* __restrict__ wp) {
    extern __shared__ __align__(16) uint8_t sm8[];
    int bx = blockIdx.x;
    if (bx < 32)
        tc_body(g_xkp, wp + (size_t)OFK_ * 4, nullptr, nullptr, g_kfp,
                4, FF_, H_, blockIdx.y * 128, bx, sm8);
    else
        tc_body(g_xrp, wp + (size_t)OFR_ * 4, g_r, nullptr, nullptr,
                1, H_, H_, blockIdx.y * 128, bx - 32, sm8);
}

// ---------------- host orchestration -----------------------------------------
extern "C" void kernel_launch(void* const* d_in, const int* in_sizes, int n_in,
                              void* d_out, int out_size) {
    (void)in_sizes; (void)n_in; (void)out_size;
    const float* x     = (const float*)d_in[0];
    const float* prew  = (const float*)d_in[1];
    const float* preb  = (const float*)d_in[2];
    const float* ln1w  = (const float*)d_in[3];
    const float* ln1b  = (const float*)d_in[4];
    const float* ln2w  = (const float*)d_in[5];
    const float* ln2b  = (const float*)d_in[6];
    const float* td    = (const float*)d_in[7];
    const float* tf    = (const float*)d_in[8];
    const float* amk   = (const float*)d_in[9];
    const float* amv   = (const float*)d_in[10];
    const float* amr   = (const float*)d_in[11];
    const float* Wk    = (const float*)d_in[12];
    const float* Wv    = (const float*)d_in[13];
    const float* Wr    = (const float*)d_in[14];
    const float* Wo    = (const float*)d_in[15];
    const float* fmk   = (const float*)d_in[16];
    const float* fmr   = (const float*)d_in[17];
    const float* Fk    = (const float*)d_in[18];
    const float* Fv    = (const float*)d_in[19];
    const float* Fr    = (const float*)d_in[20];
    const float* lnow  = (const float*)d_in[21];
    const float* lnob  = (const float*)d_in[22];
    const float* headw = (const float*)d_in[23];

    float *h, *k, *v, *r;
    char *wp, *xkp, *xvp, *xrp, *atp, *kfp;
    cudaGetSymbolAddress((void**)&h,   g_h);
    cudaGetSymbolAddress((void**)&k,   g_k);
    cudaGetSymbolAddress((void**)&v,   g_v);
    cudaGetSymbolAddress((void**)&r,   g_r);
    cudaGetSymbolAddress((void**)&wp,  g_wp);
    cudaGetSymbolAddress((void**)&xkp, g_xkp);
    cudaGetSymbolAddress((void**)&xvp, g_xvp);
    cudaGetSymbolAddress((void**)&xrp, g_xrp);
    cudaGetSymbolAddress((void**)&atp, g_atp);
    cudaGetSymbolAddress((void**)&kfp, g_kfp);

    cudaFuncSetAttribute(tgemm,     cudaFuncAttributeMaxDynamicSharedMemorySize, GEMM_SMEM);
    cudaFuncSetAttribute(tgemm_kvr, cudaFuncAttributeMaxDynamicSharedMemorySize, GEMM_SMEM);
    cudaFuncSetAttribute(tgemm_ff,  cudaFuncAttributeMaxDynamicSharedMemorySize, GEMM_SMEM);

    dim3 blk(256);
    dim3 gblk(GT_);
    dim3 tb(32, 8);
    dim3 gHHz(H_ / 32, H_ / 32, 5 * L_);
    dim3 gHFz(FF_ / 32, H_ / 32, L_);
    dim3 gFHz(H_ / 32, FF_ / 32, L_);
    dim3 gHH(H_ / 32, H_ / 32);
    dim3 gH(H_ / TN_,  BT_ / 128);        // (8, 32)
    dim3 gKVR(H_ / TN_, BT_ / 128, 3);    // (8, 32, 3)
    dim3 gFF(FF_ / TN_ + H_ / TN_, BT_ / 128);  // (40, 32)

    ln_kernel<<<BT_, blk>>>(x, prew, preb, h);
    transT_hh<<<gHHz, tb>>>(Wk, Wv, Wr, Wo, Fr, wp);
    transT_rect<<<gHFz, tb>>>(Fk, wp, H_, FF_, (size_t)OFK_);
    transT_rect<<<gFHz, tb>>>(Fv, wp, FF_, H_, (size_t)OFV_);

    for (int i = 0; i < L_; i++) {
        size_t oH  = (size_t)i * H_;
        size_t wb4 = (size_t)i * WL_ * 4;

        // --- time mixing ---
        prep_mix<<<BT_, blk>>>(h, ln1w + oH, ln1b + oH, amk + oH, amv + oH, amr + oH,
                               xkp, xvp, xrp);
        tgemm_kvr<<<gKVR, gblk, GEMM_SMEM>>>(wp + wb4);
        wkv_kernel<<<(B_ * H_ + 255) / 256, blk>>>(k, v, r, td + oH, tf + oH, atp);
        tgemm<<<gH, gblk, GEMM_SMEM>>>(atp, wp + wb4 + (size_t)OWO_ * 4,
                                       h, nullptr, nullptr, 2, H_, H_);

        // --- channel mixing ---
        prep_mix<<<BT_, blk>>>(h, ln2w + oH, ln2b + oH, fmk + oH, nullptr, fmr + oH,
                               xkp, nullptr, xrp);
        tgemm_ff<<<gFF, gblk, GEMM_SMEM>>>(wp + wb4);
        tgemm<<<gH, gblk, GEMM_SMEM>>>(kfp, wp + wb4 + (size_t)OFV_ * 4,
                                       h, r, nullptr, 3, H_, FF_);
    }

    size_t hb4 = (size_t)L_ * WL_ * 4;
    transT<<<gHH, tb>>>(headw, wp + hb4, H_, H_);
    ln_split<<<BT_, blk>>>(h, lnow, lnob, xkp);
    tgemm<<<gH, gblk, GEMM_SMEM>>>(xkp, wp + hb4,
                                   (float*)d_out, nullptr, nullptr, 0, H_, H_);
}

// round 16
// speedup vs baseline: 1.5816x; 1.4433x over previous
#include <cuda_runtime.h>
#include <cuda_fp16.h>
#include <cstdint>

#define B_   8
#define T_   512
#define H_   768
#define L_   12
#define FF_  3072
#define BT_  (B_*T_)
#define EPS_ 1e-5f

#define H2_  (H_*H_)
#define HFF_ (H_*FF_)
#define WL_  (5*H2_ + 2*HFF_)
#define WTOT_ ((size_t)L_*WL_ + H2_)

#define OWK_ 0
#define OWV_ (1*H2_)
#define OWR_ (2*H2_)
#define OWO_ (3*H2_)
#define OFR_ (4*H2_)
#define OFK_ (5*H2_)
#define OFV_ (5*H2_ + HFF_)

#define LOSC_ 2048.f
#define ILOSC_ (1.f/2048.f)

// ---------------- scratch (static device globals; no allocation) ----------
__device__ float g_h[BT_*H_];
__device__ float g_k[BT_*H_];
__device__ float g_v[BT_*H_];
__device__ float g_r[BT_*H_];

// packed, pre-swizzled operand buffers (fp16 hi/lo halves per block)
// A blocks: 128 rows x 32 cols, hi 8KB + lo 8KB = 16KB per block
// W blocks:  96 rows x 32 cols, hi 6KB + lo 6KB = 12KB per block
__device__ __align__(1024) char g_wp [WTOT_*4];
__device__ __align__(1024) char g_xkp[(size_t)BT_*H_*4];
__device__ __align__(1024) char g_xvp[(size_t)BT_*H_*4];
__device__ __align__(1024) char g_xrp[(size_t)BT_*H_*4];
__device__ __align__(1024) char g_atp[(size_t)BT_*H_*4];
__device__ __align__(1024) char g_kfp[(size_t)BT_*FF_*4];

// ---------------- helpers ---------------------------------------------------
// fp16 split: hi = rn(x); lo = rn((x - hi) * 2048) (scaled out of subnormals)
__device__ __forceinline__ void fsplit(float x, __half& h, __half& l) {
    h = __float2half_rn(x);
    l = __float2half_rn((x - __half2float(h)) * LOSC_);
}

__device__ __forceinline__ float bsum256(float val, float* red) {
    int lane = threadIdx.x & 31;
    int w    = threadIdx.x >> 5;
#pragma unroll
    for (int o = 16; o; o >>= 1) val += __shfl_xor_sync(0xffffffffu, val, o);
    __syncthreads();
    if (lane == 0) red[w] = val;
    __syncthreads();
    float s = 0.f;
#pragma unroll
    for (int i = 0; i < 8; i++) s += red[i];
    return s;
}

// swizzled 16B-chunk offset within a tile (row, k-group)
__device__ __forceinline__ uint32_t goff(int row, int kg) {
    int p = row >> 1;
    int c = (kg ^ (p & 3)) | ((row & 1) << 2);
    return (uint32_t)((p * 8 + c) * 16);
}

// byte offset of element (m, j) inside a packed A buffer with K columns
__device__ __forceinline__ size_t packA(int m, int j, int K) {
    return ((size_t)(m >> 7) * (K >> 5) + (j >> 5)) * 16384
         + goff(m & 127, (j >> 3) & 3) + (j & 7) * 2;
}

// ---------------- weight transpose + split -> packed W blocks ---------------
__device__ __forceinline__ void transT_body(const float* __restrict__ in,
                                            char* __restrict__ op,
                                            int Kd, int Nd) {
    __shared__ float t[32][33];
    int n0 = blockIdx.x * 32, k0 = blockIdx.y * 32;
    int tx = threadIdx.x, ty = threadIdx.y;   // 32 x 8
#pragma unroll
    for (int i = 0; i < 32; i += 8)
        t[ty + i][tx] = in[(size_t)(k0 + ty + i) * Nd + n0 + tx];
    __syncthreads();
    int nkt = Kd >> 5;
    int kt  = k0 >> 5;
#pragma unroll
    for (int i = 0; i < 32; i += 8) {
        int n = n0 + ty + i;
        int nt = n / 96, r = n - nt * 96;
        float x = t[tx][ty + i];
        __half h, l; fsplit(x, h, l);
        size_t off = ((size_t)nt * nkt + kt) * 12288 + goff(r, (tx >> 3) & 3) + (tx & 7) * 2;
        *(__half*)(op + off)        = h;
        *(__half*)(op + off + 6144) = l;
    }
}

__global__ void transT(const float* __restrict__ in, char* __restrict__ op,
                       int Kd, int Nd) {
    transT_body(in, op, Kd, Nd);
}

__global__ void transT_hh(const float* __restrict__ p0, const float* __restrict__ p1,
                          const float* __restrict__ p2, const float* __restrict__ p3,
                          const float* __restrict__ p4, char* __restrict__ wp) {
    int z = blockIdx.z;
    int type = z / L_, layer = z % L_;
    const float* src = (type == 0) ? p0 : (type == 1) ? p1 : (type == 2) ? p2
                     : (type == 3) ? p3 : p4;
    size_t ooff = ((size_t)layer * WL_ +
        ((type == 0) ? OWK_ : (type == 1) ? OWV_ : (type == 2) ? OWR_
       : (type == 3) ? OWO_ : OFR_)) * 4;
    transT_body(src + (size_t)layer * H2_, wp + ooff, H_, H_);
}

__global__ void transT_rect(const float* __restrict__ p, char* __restrict__ wp,
                            int Kd, int Nd, size_t ooff_elem) {
    int layer = blockIdx.z;
    size_t o = ((size_t)layer * WL_ + ooff_elem) * 4;
    transT_body(p + (size_t)layer * Kd * Nd, wp + o, Kd, Nd);
}

// ---------------- LayerNorms -------------------------------------------------
__global__ void ln_kernel(const float* __restrict__ in,
                          const float* __restrict__ w,
                          const float* __restrict__ b,
                          float* __restrict__ out) {
    __shared__ float red[8];
    size_t base = (size_t)blockIdx.x * H_;
    float c[3];
    float s = 0.f, s2 = 0.f;
#pragma unroll
    for (int i = 0; i < 3; i++) {
        int j = threadIdx.x + i * 256;
        c[i] = in[base + j];
        s += c[i]; s2 += c[i] * c[i];
    }
    s  = bsum256(s,  red);
    s2 = bsum256(s2, red);
    float m = s / H_, v = s2 / H_ - m * m, rs = rsqrtf(v + EPS_);
#pragma unroll
    for (int i = 0; i < 3; i++) {
        int j = threadIdx.x + i * 256;
        out[base + j] = (c[i] - m) * rs * w[j] + b[j];
    }
}

__global__ void ln_split(const float* __restrict__ in,
                         const float* __restrict__ w,
                         const float* __restrict__ b,
                         char* __restrict__ op) {
    __shared__ float red[8];
    int row = blockIdx.x;
    size_t base = (size_t)row * H_;
    float c[3];
    float s = 0.f, s2 = 0.f;
#pragma unroll
    for (int i = 0; i < 3; i++) {
        int j = threadIdx.x + i * 256;
        c[i] = in[base + j];
        s += c[i]; s2 += c[i] * c[i];
    }
    s  = bsum256(s,  red);
    s2 = bsum256(s2, red);
    float m = s / H_, v = s2 / H_ - m * m, rs = rsqrtf(v + EPS_);
#pragma unroll
    for (int i = 0; i < 3; i++) {
        int j = threadIdx.x + i * 256;
        float x = (c[i] - m) * rs * w[j] + b[j];
        __half h, l; fsplit(x, h, l);
        size_t off = packA(row, j, H_);
        *(__half*)(op + off)        = h;
        *(__half*)(op + off + 8192) = l;
    }
}

// ---------------- LN + token-shift + lerp-mix -> packed ----------------------
__global__ void prep_mix(const float* __restrict__ hbuf,
                         const float* __restrict__ lnw, const float* __restrict__ lnb,
                         const float* __restrict__ mk,  const float* __restrict__ mv,
                         const float* __restrict__ mr,
                         char* __restrict__ xkp, char* __restrict__ xvp,
                         char* __restrict__ xrp) {
    __shared__ float red[8];
    int row = blockIdx.x;
    int t   = row % T_;
    const float* cur = hbuf + (size_t)row * H_;
    float c[3], p[3];
    float sc = 0.f, sc2 = 0.f, sp = 0.f, sp2 = 0.f;
#pragma unroll
    for (int i = 0; i < 3; i++) {
        int j = threadIdx.x + i * 256;
        c[i] = cur[j];
        sc += c[i]; sc2 += c[i] * c[i];
        p[i] = (t > 0) ? cur[j - H_] : 0.f;
        sp += p[i]; sp2 += p[i] * p[i];
    }
    sc  = bsum256(sc,  red);
    sc2 = bsum256(sc2, red);
    sp  = bsum256(sp,  red);
    sp2 = bsum256(sp2, red);
    float mc = sc / H_, vc = sc2 / H_ - mc * mc, rc = rsqrtf(vc + EPS_);
    float mp = sp / H_, vp = sp2 / H_ - mp * mp, rp = rsqrtf(vp + EPS_);
#pragma unroll
    for (int i = 0; i < 3; i++) {
        int j = threadIdx.x + i * 256;
        float w = lnw[j], bb = lnb[j];
        float hn = (c[i] - mc) * rc * w + bb;
        float sh = (t > 0) ? ((p[i] - mp) * rp * w + bb) : 0.f;
        size_t off = packA(row, j, H_);
        __half hh, ll;
        float k_ = mk[j];
        fsplit(hn * k_ + sh * (1.f - k_), hh, ll);
        *(__half*)(xkp + off)        = hh;
        *(__half*)(xkp + off + 8192) = ll;
        if (xvp) {
            float v_ = mv[j];
            fsplit(hn * v_ + sh * (1.f - v_), hh, ll);
            *(__half*)(xvp + off)        = hh;
            *(__half*)(xvp + off + 8192) = ll;
        }
        float r_ = mr[j];
        fsplit(hn * r_ + sh * (1.f - r_), hh, ll);
        *(__half*)(xrp + off)        = hh;
        *(__half*)(xrp + off + 8192) = ll;
    }
}

// ---------------- WKV scan -> packed, software-pipelined ----------------------
#define WG_ 16
__global__ void wkv_kernel(const float* __restrict__ k,
                           const float* __restrict__ v,
                           const float* __restrict__ r,
                           const float* __restrict__ td,
                           const float* __restrict__ tf,
                           char* __restrict__ atp) {
    int c = blockIdx.x * blockDim.x + threadIdx.x;
    if (c >= B_ * H_) return;
    int b = c / H_, hh = c % H_;
    float w = -expf(td[hh]);
    float u = tf[hh];
    float num = 0.f, den = 0.f, mx = -1e38f;
    size_t base = (size_t)b * T_ * H_ + hh;
    int kt = hh >> 5, kg = (hh >> 3) & 3, byo = (hh & 7) * 2;

    float ka[WG_], va[WG_], ra[WG_];
    float kb[WG_], vb[WG_], rb[WG_];

    auto stage = [&](float (&kq)[WG_], float (&vq)[WG_], float (&rq)[WG_], int g) {
#pragma unroll
        for (int j = 0; j < WG_; j++) {
            size_t i = base + (size_t)(g * WG_ + j) * H_;
            kq[j] = k[i]; vq[j] = v[i]; rq[j] = r[i];
        }
    };
    auto work = [&](float (&kq)[WG_], float (&vq)[WG_], float (&rq)[WG_], int g) {
#pragma unroll
        for (int j = 0; j < WG_; j++) {
            int t = g * WG_ + j;
            float kt_ = kq[j], vt = vq[j];
            float a  = kt_ + u;
            float mo = fmaxf(mx, a);
            float e1 = expf(mx - mo), e2 = expf(a - mo);
            float out = ((e1 * num + e2 * vt) / (e1 * den + e2)) * rq[j];
            __half oh, ol; fsplit(out, oh, ol);
            int row = b * T_ + t;
            size_t off = ((size_t)(row >> 7) * (H_ >> 5) + kt) * 16384
                       + goff(row & 127, kg) + byo;
            *(__half*)(atp + off)        = oh;
            *(__half*)(atp + off + 8192) = ol;
            float ms = fmaxf(mx + w, kt_);
            float f1 = expf(mx + w - ms), f2 = expf(kt_ - ms);
            num = f1 * num + f2 * vt;
            den = f1 * den + f2;
            mx  = ms;
        }
    };

    const int NG = T_ / WG_;   // 32
    stage(ka, va, ra, 0);
#pragma unroll 1
    for (int g = 0; g < NG; g += 2) {
        if (g + 1 < NG) stage(kb, vb, rb, g + 1);
        work(ka, va, ra, g);
        if (g + 2 < NG) stage(ka, va, ra, g + 2);
        if (g + 1 < NG) work(kb, vb, rb, g + 1);
    }
}

// ====================== fp16 split tensor-core GEMM =========================
// Tile 128x96, 256 threads = 8 warps (2x4), warp tile 64x24. K-tile 32,
// 4-stage cp.async.bulk pipeline (R13/R15 skeleton).
// Pass 1 (ah*bh): f32 accumulator. Passes 2+3 (al*bh + ah*bl, lo scaled
// x2048): shared f16 accumulator (hypothesis: f16-acc HMMA is double rate).
// epi: 0 C=v, 1 C=sigmoid(v), 2 C+=v, 3 C+=aux*v, 4 Op=packed split(relu(v)^2)

#define TN_     96
#define AL_OFF  8192
#define BH_OFF  16384
#define BL_OFF  22528
#define STG_B   28672
#define NSTG    4
#define GEMM_SMEM (NSTG*STG_B)
#define GT_     256

__device__ __forceinline__ void mbar_init(uint32_t a, uint32_t cnt) {
    asm volatile("mbarrier.init.shared.b64 [%0], %1;" :: "r"(a), "r"(cnt) : "memory");
}
__device__ __forceinline__ void mbar_wait(uint32_t a, uint32_t parity) {
    asm volatile(
        "{ .reg .pred P;\n"
        "WL_%=: mbarrier.try_wait.parity.acquire.cta.shared::cta.b64 P, [%0], %1, 0x989680;\n"
        "@P bra WD_%=;\n"
        "bra WL_%=;\n"
        "WD_%=: }\n" :: "r"(a), "r"(parity) : "memory");
}
__device__ __forceinline__ void mbar_expect_tx(uint32_t a, uint32_t bytes) {
    asm volatile("mbarrier.arrive.expect_tx.shared.b64 _, [%0], %1;"
                 :: "r"(a), "r"(bytes) : "memory");
}
__device__ __forceinline__ void bulk_g2s(uint32_t dst, const void* src,
                                         uint32_t bytes, uint32_t mbar) {
    asm volatile(
        "cp.async.bulk.shared::cta.global.mbarrier::complete_tx::bytes [%0], [%1], %2, [%3];"
        :: "r"(dst), "l"(src), "r"(bytes), "r"(mbar) : "memory");
}
__device__ __forceinline__ void ldsm4(uint32_t r[4], uint32_t a) {
    asm volatile("ldmatrix.sync.aligned.m8n8.x4.shared.b16 {%0,%1,%2,%3}, [%4];\n"
                 : "=r"(r[0]), "=r"(r[1]), "=r"(r[2]), "=r"(r[3]) : "r"(a));
}
__device__ __forceinline__ void ldsm2(uint32_t r[2], uint32_t a) {
    asm volatile("ldmatrix.sync.aligned.m8n8.x2.shared.b16 {%0,%1}, [%2];\n"
                 : "=r"(r[0]), "=r"(r[1]) : "r"(a));
}
// f16 inputs, f32 accumulator
__device__ __forceinline__ void mma_f32(float c[4], const uint32_t a[4],
                                        uint32_t b0, uint32_t b1) {
    asm volatile(
        "mma.sync.aligned.m16n8k16.row.col.f32.f16.f16.f32 "
        "{%0,%1,%2,%3}, {%4,%5,%6,%7}, {%8,%9}, {%0,%1,%2,%3};\n"
        : "+f"(c[0]), "+f"(c[1]), "+f"(c[2]), "+f"(c[3])
        : "r"(a[0]), "r"(a[1]), "r"(a[2]), "r"(a[3]), "r"(b0), "r"(b1));
}
// f16 inputs, f16 accumulator (2 packed regs)
__device__ __forceinline__ void mma_f16(uint32_t c[2], const uint32_t a[4],
                                        uint32_t b0, uint32_t b1) {
    asm volatile(
        "mma.sync.aligned.m16n8k16.row.col.f16.f16.f16.f16 "
        "{%0,%1}, {%2,%3,%4,%5}, {%6,%7}, {%0,%1};\n"
        : "+r"(c[0]), "+r"(c[1])
        : "r"(a[0]), "r"(a[1]), "r"(a[2]), "r"(a[3]), "r"(b0), "r"(b1));
}

__device__ __forceinline__ void tc_body(
    const char* __restrict__ Ap, const char* __restrict__ Bp,
    float* __restrict__ C, const float* __restrict__ aux,
    char* __restrict__ Op,
    int epi, int N, int K, int bm, int bnt, uint8_t* sm8) {

    __shared__ uint64_t s_mb[NSTG];
    uint32_t sb = (uint32_t)__cvta_generic_to_shared(sm8);
    uint32_t mb = (uint32_t)__cvta_generic_to_shared(&s_mb[0]);

    int tid = threadIdx.x;
    int l   = tid & 31;
    int w   = tid >> 5;        // 0..7
    int wm  = w >> 2;          // 0..1
    int wn  = w & 3;           // 0..3
    int sub = l >> 3;
    int bn  = bnt * TN_;
    int nkt = K >> 5;

    if (tid == 0) {
#pragma unroll
        for (int s = 0; s < NSTG; s++) mbar_init(mb + 8*s, 1);
    }
    __syncthreads();

    auto issue = [&](int i) {
        int s = i & (NSTG - 1);
        uint32_t st = sb + s * STG_B;
        mbar_expect_tx(mb + 8*s, STG_B);
        size_t ab = ((size_t)(bm >> 7) * nkt + i) * 16384;
        size_t bb = ((size_t)bnt * nkt + i) * 12288;
        bulk_g2s(st,          Ap + ab, 16384, mb + 8*s);
        bulk_g2s(st + BH_OFF, Bp + bb, 12288, mb + 8*s);
    };
    if (tid == 0) { issue(0); issue(1); issue(2); issue(3); }

    float    accf[4][3][4];
    uint32_t acch[4][3][2];
#pragma unroll
    for (int mi = 0; mi < 4; mi++)
#pragma unroll
        for (int ni = 0; ni < 3; ni++) {
#pragma unroll
            for (int q = 0; q < 4; q++) accf[mi][ni][q] = 0.f;
            acch[mi][ni][0] = 0u; acch[mi][ni][1] = 0u;
        }

    int arow0 = wm * 64 + (l & 7) + ((sub & 1) << 3);
    int brow0 = wn * 24 + (l & 7) + ((sub >> 1) << 3);   // rows 0..15 of warp's 24
    int brow2 = wn * 24 + 16 + (l & 7);                  // rows 16..23 (x2)
    int akg_  = (sub >> 1);
    int bkg_  = (sub & 1);
    int bkg2_ = (l >> 3) & 1;

#pragma unroll 1
    for (int i = 0; i < nkt; i++) {
        int s = i & (NSTG - 1);
        mbar_wait(mb + 8*s, (i >> 2) & 1);
        uint32_t st = sb + s * STG_B;

#pragma unroll
        for (int ks = 0; ks < 2; ks++) {
            int akg  = ks * 2 + akg_;
            int bkg  = ks * 2 + bkg_;
            int bkg2 = ks * 2 + bkg2_;

            uint32_t ah[4][4], bh[4], bx[2], al[4][4], blh[4], blx[2];
#pragma unroll
            for (int mi = 0; mi < 4; mi++) ldsm4(ah[mi], st + goff(arow0 + mi * 16, akg));
            ldsm4(bh, st + BH_OFF + goff(brow0, bkg));
            ldsm2(bx, st + BH_OFF + goff(brow2, bkg2));

            // pass 1: ah * bh -> f32 acc
#pragma unroll
            for (int mi = 0; mi < 4; mi++) {
                mma_f32(accf[mi][0], ah[mi], bh[0], bh[1]);
                mma_f32(accf[mi][1], ah[mi], bh[2], bh[3]);
                mma_f32(accf[mi][2], ah[mi], bx[0], bx[1]);
            }
            // pass 2: al * bh -> f16 acc
#pragma unroll
            for (int mi = 0; mi < 4; mi++) ldsm4(al[mi], st + AL_OFF + goff(arow0 + mi * 16, akg));
#pragma unroll
            for (int mi = 0; mi < 4; mi++) {
                mma_f16(acch[mi][0], al[mi], bh[0], bh[1]);
                mma_f16(acch[mi][1], al[mi], bh[2], bh[3]);
                mma_f16(acch[mi][2], al[mi], bx[0], bx[1]);
            }
            // pass 3: ah * bl -> f16 acc
            ldsm4(blh, st + BL_OFF + goff(brow0, bkg));
            ldsm2(blx, st + BL_OFF + goff(brow2, bkg2));
#pragma unroll
            for (int mi = 0; mi < 4; mi++) {
                mma_f16(acch[mi][0], ah[mi], blh[0], blh[1]);
                mma_f16(acch[mi][1], ah[mi], blh[2], blh[3]);
                mma_f16(acch[mi][2], ah[mi], blx[0], blx[1]);
            }
        }

        __syncthreads();
        if (tid == 0 && i + NSTG < nkt) issue(i + NSTG);
    }

    // ---- epilogue ----
#pragma unroll
    for (int mi = 0; mi < 4; mi++) {
#pragma unroll
        for (int ni = 0; ni < 3; ni++) {
            int r0 = bm + wm * 64 + mi * 16 + (l >> 2);
            int c0 = bn + wn * 24 + ni * 8 + (l & 3) * 2;
            __half2 p0 = *reinterpret_cast<__half2*>(&acch[mi][ni][0]);
            __half2 p1 = *reinterpret_cast<__half2*>(&acch[mi][ni][1]);
            float cf[4] = {__low2float(p0), __high2float(p0),
                           __low2float(p1), __high2float(p1)};
#pragma unroll
            for (int q = 0; q < 4; q++) {
                int rr = r0 + (q >> 1) * 8;
                int cc = c0 + (q & 1);
                float v = accf[mi][ni][q] + cf[q] * ILOSC_;
                if (epi == 4) {
                    float qq = fmaxf(v, 0.f); qq = qq * qq;
                    __half hh, ll; fsplit(qq, hh, ll);
                    size_t off = packA(rr, cc, N);
                    *(__half*)(Op + off)        = hh;
                    *(__half*)(Op + off + 8192) = ll;
                } else {
                    size_t idx = (size_t)rr * N + cc;
                    if (epi == 0)      C[idx] = v;
                    else if (epi == 1) C[idx] = 1.f / (1.f + expf(-v));
                    else if (epi == 2) C[idx] += v;
                    else               C[idx] += aux[idx] * v;
                }
            }
        }
    }
}

// ---- kernel wrappers ----
__global__ __launch_bounds__(GT_, 2) void tgemm(
    const char* __restrict__ Ap, const char* __restrict__ Bp,
    float* C, const float* aux, char* Op, int epi, int N, int K) {
    extern __shared__ __align__(16) uint8_t sm8[];
    tc_body(Ap, Bp, C, aux, Op, epi, N, K, blockIdx.y * 128, blockIdx.x, sm8);
}

// batched k/v/r: grid (8, 32, 3)
__global__ __launch_bounds__(GT_, 2) void tgemm_kvr(const char* __restrict__ wp) {
    extern __shared__ __align__(16) uint8_t sm8[];
    int z = blockIdx.z;
    const char* Ap = (z == 0) ? g_xkp : (z == 1) ? g_xvp : g_xrp;
    size_t wo = ((z == 0) ? (size_t)OWK_ : (z == 1) ? (size_t)OWV_ : (size_t)OWR_) * 4;
    float* C = (z == 0) ? g_k : (z == 1) ? g_v : g_r;
    tc_body(Ap, wp + wo, C, nullptr, nullptr, (z == 2) ? 1 : 0, H_, H_,
            blockIdx.y * 128, blockIdx.x, sm8);
}

// batched Fk (x<32) + Fr (x>=32): grid (40, 32)
__global__ __launch_bounds__(GT_, 2) void tgemm_ff(const char* __restrict__ wp) {
    extern __shared__ __align__(16) uint8_t sm8[];
    int bx = blockIdx.x;
    if (bx < 32)
        tc_body(g_xkp, wp + (size_t)OFK_ * 4, nullptr, nullptr, g_kfp,
                4, FF_, H_, blockIdx.y * 128, bx, sm8);
    else
        tc_body(g_xrp, wp + (size_t)OFR_ * 4, g_r, nullptr, nullptr,
                1, H_, H_, blockIdx.y * 128, bx - 32, sm8);
}

// ---------------- host orchestration -----------------------------------------
extern "C" void kernel_launch(void* const* d_in, const int* in_sizes, int n_in,
                              void* d_out, int out_size) {
    (void)in_sizes; (void)n_in; (void)out_size;
    const float* x     = (const float*)d_in[0];
    const float* prew  = (const float*)d_in[1];
    const float* preb  = (const float*)d_in[2];
    const float* ln1w  = (const float*)d_in[3];
    const float* ln1b  = (const float*)d_in[4];
    const float* ln2w  = (const float*)d_in[5];
    const float* ln2b  = (const float*)d_in[6];
    const float* td    = (const float*)d_in[7];
    const float* tf    = (const float*)d_in[8];
    const float* amk   = (const float*)d_in[9];
    const float* amv   = (const float*)d_in[10];
    const float* amr   = (const float*)d_in[11];
    const float* Wk    = (const float*)d_in[12];
    const float* Wv    = (const float*)d_in[13];
    const float* Wr    = (const float*)d_in[14];
    const float* Wo    = (const float*)d_in[15];
    const float* fmk   = (const float*)d_in[16];
    const float* fmr   = (const float*)d_in[17];
    const float* Fk    = (const float*)d_in[18];
    const float* Fv    = (const float*)d_in[19];
    const float* Fr    = (const float*)d_in[20];
    const float* lnow  = (const float*)d_in[21];
    const float* lnob  = (const float*)d_in[22];
    const float* headw = (const float*)d_in[23];

    float *h, *k, *v, *r;
    char *wp, *xkp, *xvp, *xrp, *atp, *kfp;
    cudaGetSymbolAddress((void**)&h,   g_h);
    cudaGetSymbolAddress((void**)&k,   g_k);
    cudaGetSymbolAddress((void**)&v,   g_v);
    cudaGetSymbolAddress((void**)&r,   g_r);
    cudaGetSymbolAddress((void**)&wp,  g_wp);
    cudaGetSymbolAddress((void**)&xkp, g_xkp);
    cudaGetSymbolAddress((void**)&xvp, g_xvp);
    cudaGetSymbolAddress((void**)&xrp, g_xrp);
    cudaGetSymbolAddress((void**)&atp, g_atp);
    cudaGetSymbolAddress((void**)&kfp, g_kfp);

    cudaFuncSetAttribute(tgemm,     cudaFuncAttributeMaxDynamicSharedMemorySize, GEMM_SMEM);
    cudaFuncSetAttribute(tgemm_kvr, cudaFuncAttributeMaxDynamicSharedMemorySize, GEMM_SMEM);
    cudaFuncSetAttribute(tgemm_ff,  cudaFuncAttributeMaxDynamicSharedMemorySize, GEMM_SMEM);

    dim3 blk(256);
    dim3 gblk(GT_);
    dim3 tb(32, 8);
    dim3 gHHz(H_ / 32, H_ / 32, 5 * L_);
    dim3 gHFz(FF_ / 32, H_ / 32, L_);
    dim3 gFHz(H_ / 32, FF_ / 32, L_);
    dim3 gHH(H_ / 32, H_ / 32);
    dim3 gH(H_ / TN_,  BT_ / 128);        // (8, 32)
    dim3 gKVR(H_ / TN_, BT_ / 128, 3);    // (8, 32, 3)
    dim3 gFF(FF_ / TN_ + H_ / TN_, BT_ / 128);  // (40, 32)

    ln_kernel<<<BT_, blk>>>(x, prew, preb, h);
    transT_hh<<<gHHz, tb>>>(Wk, Wv, Wr, Wo, Fr, wp);
    transT_rect<<<gHFz, tb>>>(Fk, wp, H_, FF_, (size_t)OFK_);
    transT_rect<<<gFHz, tb>>>(Fv, wp, FF_, H_, (size_t)OFV_);

    for (int i = 0; i < L_; i++) {
        size_t oH  = (size_t)i * H_;
        size_t wb4 = (size_t)i * WL_ * 4;

        // --- time mixing ---
        prep_mix<<<BT_, blk>>>(h, ln1w + oH, ln1b + oH, amk + oH, amv + oH, amr + oH,
                               xkp, xvp, xrp);
        tgemm_kvr<<<gKVR, gblk, GEMM_SMEM>>>(wp + wb4);
        wkv_kernel<<<(B_ * H_ + 255) / 256, blk>>>(k, v, r, td + oH, tf + oH, atp);
        tgemm<<<gH, gblk, GEMM_SMEM>>>(atp, wp + wb4 + (size_t)OWO_ * 4,
                                       h, nullptr, nullptr, 2, H_, H_);

        // --- channel mixing ---
        prep_mix<<<BT_, blk>>>(h, ln2w + oH, ln2b + oH, fmk + oH, nullptr, fmr + oH,
                               xkp, nullptr, xrp);
        tgemm_ff<<<gFF, gblk, GEMM_SMEM>>>(wp + wb4);
        tgemm<<<gH, gblk, GEMM_SMEM>>>(kfp, wp + wb4 + (size_t)OFV_ * 4,
                                       h, r, nullptr, 3, H_, FF_);
    }

    size_t hb4 = (size_t)L_ * WL_ * 4;
    transT<<<gHH, tb>>>(headw, wp + hb4, H_, H_);
    ln_split<<<BT_, blk>>>(h, lnow, lnob, xkp);
    tgemm<<<gH, gblk, GEMM_SMEM>>>(xkp, wp + hb4,
                                   (float*)d_out, nullptr, nullptr, 0, H_, H_);
}